// round 3
// baseline (speedup 1.0000x reference)
#include <cuda_runtime.h>
#include <cstdint>

// Problem constants (fixed shapes from reference)
#define BB   16
#define NN   2000
#define CC   20
#define NPAD 2048          // next pow2 >= NN for bitonic sort
#define NW   32            // ceil(NN/64) 64-bit mask words per row
#define NB64 32            // number of 64-row blocks
#define WIMG 602.0f
#define MINB 5.0f
#define BCT  0.01f
#define CTHR 0.001f
#define IOUT 0.2f
#define MAXWH 4096.0f

// ---------------- static device scratch (no allocations allowed) ----------------
__device__ unsigned long long g_keys[BB][NPAD];      // sort keys
__device__ float4             g_sbox[BB][NN];        // sorted boxes + class offset (for IoU)
__device__ float4             g_obox[BB][NN];        // sorted boxes, original clipped (for output)
__device__ float              g_sarea[BB][NN];       // area of offset box (matches ref float order)
__device__ float              g_sscore[BB][NN];
__device__ int                g_scls[BB][NN];
__device__ int                g_svalid[BB][NN];
__device__ unsigned long long g_mask[BB][NN][NW];    // suppression bitmask rows (8.2 MB)
__device__ unsigned long long g_removed[BB][NW];

__device__ __forceinline__ float neg_inf_f() { return __uint_as_float(0xff800000u); }

// Compute sort key for proposal (b, n): monotone(score or -inf) << 32 | ~n
__device__ __forceinline__ unsigned long long make_key(
    const float* __restrict__ prop, const float* __restrict__ preds,
    const float* __restrict__ bscp, int b, int n)
{
    const float* p = prop + ((size_t)b * NN + n) * 4;
    float x1 = fminf(fmaxf(p[0], 0.f), WIMG);
    float y1 = fminf(fmaxf(p[1], 0.f), WIMG);
    float x2 = fminf(fmaxf(p[2], 0.f), WIMG);
    float y2 = fminf(fmaxf(p[3], 0.f), WIMG);

    const float* pd = preds + ((size_t)b * NN + n) * CC;
    float best = pd[0];
#pragma unroll
    for (int c = 1; c < CC; c++) { float v = pd[c]; if (v > best) best = v; }

    float bsc = bscp[b * NN + n];
    float s = bsc * best;
    bool valid = (bsc > BCT) && ((x2 - x1) >= MINB) && ((y2 - y1) >= MINB) && (s > CTHR);

    float sv = valid ? s : neg_inf_f();
    unsigned u = __float_as_uint(sv);
    u = (u & 0x80000000u) ? ~u : (u | 0x80000000u);     // monotone float->uint map
    return ((unsigned long long)u << 32) | (unsigned)(~(unsigned)n);
}

// ---------------- K2: key-gen + bitonic sort (descending) of 2048 keys per image ----------------
__global__ void k2_sort(const float* __restrict__ prop,
                        const float* __restrict__ preds,
                        const float* __restrict__ bscp) {
    __shared__ unsigned long long s[NPAD];
    int b = blockIdx.x;
    int tid = threadIdx.x;                 // 1024 threads
    // compute keys inline (former k1)
    s[tid]        = (tid < NN) ? make_key(prop, preds, bscp, b, tid) : 0ull;
    int t2 = tid + 1024;
    s[t2]         = (t2 < NN) ? make_key(prop, preds, bscp, b, t2) : 0ull;
    __syncthreads();
    for (int k = 2; k <= NPAD; k <<= 1) {
        for (int j = k >> 1; j > 0; j >>= 1) {
#pragma unroll
            for (int off = 0; off < 2; off++) {
                int i = tid + off * 1024;
                int ixj = i ^ j;
                if (ixj > i) {
                    unsigned long long a = s[i], c = s[ixj];
                    bool up = ((i & k) == 0);
                    bool sw = up ? (a < c) : (a > c);   // descending overall
                    if (sw) { s[i] = c; s[ixj] = a; }
                }
            }
            __syncthreads();
        }
    }
    g_keys[b][tid]        = s[tid];
    g_keys[b][tid + 1024] = s[tid + 1024];
}

// ---------------- K3: gather sorted per-proposal data ----------------
__global__ void k3_gather(const float* __restrict__ prop,
                          const float* __restrict__ preds,
                          const float* __restrict__ bscp) {
    int t = blockIdx.x * blockDim.x + threadIdx.x;
    if (t >= BB * NN) return;
    int b = t / NN, ppos = t % NN;
    unsigned long long key = g_keys[b][ppos];
    int n = (int)(~(unsigned)key);                      // original index

    const float* p = prop + ((size_t)b * NN + n) * 4;
    float x1 = fminf(fmaxf(p[0], 0.f), WIMG);
    float y1 = fminf(fmaxf(p[1], 0.f), WIMG);
    float x2 = fminf(fmaxf(p[2], 0.f), WIMG);
    float y2 = fminf(fmaxf(p[3], 0.f), WIMG);

    const float* pd = preds + ((size_t)b * NN + n) * CC;
    float best = pd[0]; int cid = 0;
#pragma unroll
    for (int c = 1; c < CC; c++) { float v = pd[c]; if (v > best) { best = v; cid = c; } }

    float bsc = bscp[b * NN + n];
    float s = bsc * best;
    bool valid = (bsc > BCT) && ((x2 - x1) >= MINB) && ((y2 - y1) >= MINB) && (s > CTHR);

    // class-offset boxes, float add exactly as reference (rounding included)
    float off = (float)cid * MAXWH;
    float ox1 = x1 + off, oy1 = y1 + off, ox2 = x2 + off, oy2 = y2 + off;

    g_sbox[b][ppos]  = make_float4(ox1, oy1, ox2, oy2);
    g_obox[b][ppos]  = make_float4(x1, y1, x2, y2);
    g_sarea[b][ppos] = fmaxf(ox2 - ox1, 0.f) * fmaxf(oy2 - oy1, 0.f);  // ref computes area post-offset
    g_sscore[b][ppos] = s;
    g_scls[b][ppos]   = cid;
    g_svalid[b][ppos] = valid ? 1 : 0;
}

// ---------------- K4: pairwise IoU suppression mask (upper-triangular only) ----------------
__device__ __forceinline__ unsigned long long iou_bits(
    float4 bi, float ai, const float4* cbx, const float* car, int jlo, int jmax)
{
    unsigned long long m = 0ull;
#pragma unroll 4
    for (int jj = jlo; jj < jmax; jj++) {
        float4 bj = cbx[jj];
        float lx = fmaxf(bi.x, bj.x), ly = fmaxf(bi.y, bj.y);
        float rx = fminf(bi.z, bj.z), ry = fminf(bi.w, bj.w);
        float w = fmaxf(rx - lx, 0.f), h = fmaxf(ry - ly, 0.f);
        float inter = w * h;
        float uni = ai + car[jj] - inter;
        float iou = __fdiv_rn(inter, fmaxf(uni, 1e-9f));  // IEEE div even under fast-math
        if (iou > IOUT) m |= (1ull << jj);
    }
    return m;
}

__global__ void k4_mask() {
    int b  = blockIdx.z;
    int rb = blockIdx.y;       // row block (i)
    int cb = blockIdx.x;       // col block (j), 64 cols
    if (cb < rb) return;       // strictly lower-triangular blocks produce no bits
    __shared__ float4 cbx[64];
    __shared__ float  car[64];
    int j = cb * 64 + threadIdx.x;
    if (j < NN) { cbx[threadIdx.x] = g_sbox[b][j]; car[threadIdx.x] = g_sarea[b][j]; }
    else        { cbx[threadIdx.x] = make_float4(0.f,0.f,0.f,0.f); car[threadIdx.x] = 0.f; }
    __syncthreads();

    int i = rb * 64 + threadIdx.x;
    if (i >= NN) return;
    float4 bi = g_sbox[b][i];
    float  ai = g_sarea[b][i];
    int jmax = min(64, NN - cb * 64);
    unsigned long long m;
    if (cb == rb) {
        // diagonal: only jj > threadIdx.x
        m = iou_bits(bi, ai, cbx, car, threadIdx.x + 1, jmax);
    } else {
        // off-diagonal: all 64 columns are > i, no compare needed
        m = iou_bits(bi, ai, cbx, car, 0, jmax);
    }
    g_mask[b][i][cb] = m;
}

// ---------------- K5: serial greedy scan, one warp per image, diagonal-broadcast ----------------
// Lower-triangular mask words (lane < chunk for rows in `chunk`) are never
// written by triangular k4; they are structurally zero, so we predicate the
// load instead of zeroing them in a separate kernel.
__global__ void k5_reduce() {
    int img = blockIdx.x;
    int lane = threadIdx.x;                            // 32 lanes = 32 mask words
    unsigned long long rem = 0ull;
    for (int chunk = 0; chunk < NW; chunk++) {
        // removed-word for this chunk so far (includes all earlier suppressions)
        unsigned long long cur = __shfl_sync(0xffffffffu, rem, chunk);
        int base = chunk * 64;
        // pack valid bits for this chunk via ballots (all lanes get same word)
        int i0 = base + lane, i1 = base + 32 + lane;
        int v0 = (i0 < NN) ? g_svalid[img][i0] : 0;
        int v1 = (i1 < NN) ? g_svalid[img][i1] : 0;
        unsigned lo = __ballot_sync(0xffffffffu, v0 != 0);
        unsigned hi = __ballot_sync(0xffffffffu, v1 != 0);
        unsigned long long vword = ((unsigned long long)hi << 32) | lo;

        bool lane_live = (lane >= chunk);              // words below diagonal are zero
        int nmax = min(64, NN - base);
#pragma unroll 8
        for (int bb = 0; bb < nmax; bb++) {
            int i = base + bb;
            unsigned long long rowv = lane_live ? g_mask[img][i][lane] : 0ull;
            unsigned long long diag = g_mask[img][i][chunk];  // same addr all lanes: L1 broadcast
            bool alive = ((vword >> bb) & 1ull) && !((cur >> bb) & 1ull);
            if (alive) { rem |= rowv; cur |= diag; }
        }
    }
    g_removed[img][lane] = rem;
}

// ---------------- K6: write [B,N,6] output ----------------
__global__ void k6_out(float* __restrict__ out) {
    int t = blockIdx.x * blockDim.x + threadIdx.x;
    if (t >= BB * NN) return;
    int b = t / NN, p = t % NN;
    unsigned long long w = g_removed[b][p >> 6];
    bool rem = (w >> (p & 63)) & 1ull;
    bool keep = g_svalid[b][p] && !rem;
    float* o = out + ((size_t)b * NN + p) * 6;
    if (keep) {
        float4 bx = g_obox[b][p];
        o[0] = bx.x; o[1] = bx.y; o[2] = bx.z; o[3] = bx.w;
        o[4] = g_sscore[b][p];
        o[5] = (float)g_scls[b][p];
    } else {
        o[0] = 0.f; o[1] = 0.f; o[2] = 0.f; o[3] = 0.f; o[4] = 0.f; o[5] = 0.f;
    }
}

extern "C" void kernel_launch(void* const* d_in, const int* in_sizes, int n_in,
                              void* d_out, int out_size) {
    const float* prop  = (const float*)d_in[0];   // [16,2000,4]
    const float* preds = (const float*)d_in[1];   // [16,2000,20]
    const float* bsc   = (const float*)d_in[2];   // [16,2000]
    float* out = (float*)d_out;                   // [16,2000,6]

    (void)in_sizes; (void)n_in; (void)out_size;

    k2_sort<<<BB, 1024>>>(prop, preds, bsc);
    int tot2 = BB * NN;
    k3_gather<<<(tot2 + 255) / 256, 256>>>(prop, preds, bsc);
    dim3 mg(NB64, NB64, BB);
    k4_mask<<<mg, 64>>>();
    k5_reduce<<<BB, 32>>>();
    k6_out<<<(tot2 + 255) / 256, 256>>>(out);
}

// round 4
// speedup vs baseline: 2.0367x; 2.0367x over previous
#include <cuda_runtime.h>
#include <cstdint>

#define BB   16
#define NN   2000
#define CC   20
#define NPAD 2048
#define NW   32
#define NB64 32
#define WIMG 602.0f
#define MINB 5.0f
#define BCT  0.01f
#define CTHR 0.001f
#define IOUT 0.2f
#define MAXWH 4096.0f

__device__ unsigned long long g_keys[BB][NPAD];
__device__ float4             g_sbox[BB][NN];
__device__ float4             g_obox[BB][NN];
__device__ float              g_sarea[BB][NN];
__device__ float              g_sscore[BB][NN];
__device__ int                g_scls[BB][NN];
__device__ int                g_svalid[BB][NN];
__device__ unsigned long long g_mask[BB][NN][NW];
__device__ unsigned long long g_removed[BB][NW];

__device__ __forceinline__ float neg_inf_f() { return __uint_as_float(0xff800000u); }

__device__ __forceinline__ unsigned long long make_key(
    const float* __restrict__ prop, const float* __restrict__ preds,
    const float* __restrict__ bscp, int b, int n)
{
    const float* p = prop + ((size_t)b * NN + n) * 4;
    float x1 = fminf(fmaxf(p[0], 0.f), WIMG);
    float y1 = fminf(fmaxf(p[1], 0.f), WIMG);
    float x2 = fminf(fmaxf(p[2], 0.f), WIMG);
    float y2 = fminf(fmaxf(p[3], 0.f), WIMG);

    const float* pd = preds + ((size_t)b * NN + n) * CC;
    float best = pd[0];
#pragma unroll
    for (int c = 1; c < CC; c++) { float v = pd[c]; if (v > best) best = v; }

    float bsc = bscp[b * NN + n];
    float s = bsc * best;
    bool valid = (bsc > BCT) && ((x2 - x1) >= MINB) && ((y2 - y1) >= MINB) && (s > CTHR);

    float sv = valid ? s : neg_inf_f();
    unsigned u = __float_as_uint(sv);
    u = (u & 0x80000000u) ? ~u : (u | 0x80000000u);
    return ((unsigned long long)u << 32) | (unsigned)(~(unsigned)n);
}

// ---------------- K2: key-gen + bitonic sort (descending) ----------------
__global__ void k2_sort(const float* __restrict__ prop,
                        const float* __restrict__ preds,
                        const float* __restrict__ bscp) {
    __shared__ unsigned long long s[NPAD];
    int b = blockIdx.x;
    int tid = threadIdx.x;                 // 1024 threads
    s[tid] = (tid < NN) ? make_key(prop, preds, bscp, b, tid) : 0ull;
    int t2 = tid + 1024;
    s[t2]  = (t2 < NN) ? make_key(prop, preds, bscp, b, t2) : 0ull;
    __syncthreads();
    for (int k = 2; k <= NPAD; k <<= 1) {
        for (int j = k >> 1; j > 0; j >>= 1) {
#pragma unroll
            for (int off = 0; off < 2; off++) {
                int i = tid + off * 1024;
                int ixj = i ^ j;
                if (ixj > i) {
                    unsigned long long a = s[i], c = s[ixj];
                    bool up = ((i & k) == 0);
                    bool sw = up ? (a < c) : (a > c);
                    if (sw) { s[i] = c; s[ixj] = a; }
                }
            }
            __syncthreads();
        }
    }
    g_keys[b][tid]        = s[tid];
    g_keys[b][tid + 1024] = s[tid + 1024];
}

// ---------------- K3: gather sorted per-proposal data ----------------
__global__ void k3_gather(const float* __restrict__ prop,
                          const float* __restrict__ preds,
                          const float* __restrict__ bscp) {
    int t = blockIdx.x * blockDim.x + threadIdx.x;
    if (t >= BB * NN) return;
    int b = t / NN, ppos = t % NN;
    unsigned long long key = g_keys[b][ppos];
    int n = (int)(~(unsigned)key);

    const float* p = prop + ((size_t)b * NN + n) * 4;
    float x1 = fminf(fmaxf(p[0], 0.f), WIMG);
    float y1 = fminf(fmaxf(p[1], 0.f), WIMG);
    float x2 = fminf(fmaxf(p[2], 0.f), WIMG);
    float y2 = fminf(fmaxf(p[3], 0.f), WIMG);

    const float* pd = preds + ((size_t)b * NN + n) * CC;
    float best = pd[0]; int cid = 0;
#pragma unroll
    for (int c = 1; c < CC; c++) { float v = pd[c]; if (v > best) { best = v; cid = c; } }

    float bsc = bscp[b * NN + n];
    float s = bsc * best;
    bool valid = (bsc > BCT) && ((x2 - x1) >= MINB) && ((y2 - y1) >= MINB) && (s > CTHR);

    float off = (float)cid * MAXWH;
    float ox1 = x1 + off, oy1 = y1 + off, ox2 = x2 + off, oy2 = y2 + off;

    g_sbox[b][ppos]  = make_float4(ox1, oy1, ox2, oy2);
    g_obox[b][ppos]  = make_float4(x1, y1, x2, y2);
    g_sarea[b][ppos] = fmaxf(ox2 - ox1, 0.f) * fmaxf(oy2 - oy1, 0.f);
    g_sscore[b][ppos] = s;
    g_scls[b][ppos]   = cid;
    g_svalid[b][ppos] = valid ? 1 : 0;
}

// ---------------- K4: pairwise IoU suppression mask (upper-triangular, div-free) ----------------
__device__ __forceinline__ unsigned long long iou_bits(
    float4 bi, float ai, const float4* cbx, const float* car, int jlo, int jmax)
{
    unsigned long long m = 0ull;
#pragma unroll 4
    for (int jj = jlo; jj < jmax; jj++) {
        float4 bj = cbx[jj];
        float lx = fmaxf(bi.x, bj.x), ly = fmaxf(bi.y, bj.y);
        float rx = fminf(bi.z, bj.z), ry = fminf(bi.w, bj.w);
        float w = fmaxf(rx - lx, 0.f), h = fmaxf(ry - ly, 0.f);
        float inter = w * h;
        float uni = fmaxf(ai + car[jj] - inter, 1e-9f);
        // iou > IOUT  <=>  inter - IOUT*uni > 0  (single FFMA, no division)
        if (fmaf(-IOUT, uni, inter) > 0.f) m |= (1ull << jj);
    }
    return m;
}

__global__ void k4_mask() {
    int b  = blockIdx.z;
    int rb = blockIdx.y;
    int cb = blockIdx.x;
    if (cb < rb) return;                     // lower triangle produces no bits
    __shared__ float4 cbx[64];
    __shared__ float  car[64];
    int j = cb * 64 + threadIdx.x;
    if (j < NN) { cbx[threadIdx.x] = g_sbox[b][j]; car[threadIdx.x] = g_sarea[b][j]; }
    else        { cbx[threadIdx.x] = make_float4(0.f,0.f,0.f,0.f); car[threadIdx.x] = 0.f; }
    __syncthreads();

    int i = rb * 64 + threadIdx.x;
    if (i >= NN) return;
    float4 bi = g_sbox[b][i];
    float  ai = g_sarea[b][i];
    int jmax = min(64, NN - cb * 64);
    unsigned long long m;
    if (cb == rb) m = iou_bits(bi, ai, cbx, car, threadIdx.x + 1, jmax);
    else          m = iou_bits(bi, ai, cbx, car, 0, jmax);
    g_mask[b][i][cb] = m;
}

// ---------------- K5: greedy scan, register-resident 64x64 chunk resolve ----------------
// Per chunk: transpose the diagonal bit-block into every lane's registers via
// ballots, run the inherently-serial 64-step recurrence purely in registers
// (no memory / no shfl on the chain), then apply alive rows' mask words.
__global__ void __launch_bounds__(32) k5_reduce() {
    const unsigned FULL = 0xffffffffu;
    int img = blockIdx.x;
    int lane = threadIdx.x;
    unsigned long long rem = 0ull;
    for (int chunk = 0; chunk < NW; chunk++) {
        unsigned long long cur0 = __shfl_sync(FULL, rem, chunk);  // earlier-chunk suppression of this chunk
        int base = chunk * 64;
        int i0 = base + lane, i1 = base + 32 + lane;
        int v0 = (i0 < NN) ? g_svalid[img][i0] : 0;
        int v1 = (i1 < NN) ? g_svalid[img][i1] : 0;
        unsigned long long d0 = (i0 < NN) ? g_mask[img][i0][chunk] : 0ull;  // diag word, row i0
        unsigned long long d1 = (i1 < NN) ? g_mask[img][i1][chunk] : 0ull;  // diag word, row i1
        unsigned lo = __ballot_sync(FULL, v0 != 0);
        unsigned hi = __ballot_sync(FULL, v1 != 0);
        unsigned long long elig = ((((unsigned long long)hi << 32) | lo)) & ~cur0;

        // transpose 64x64 diagonal block: colT[c] = set of rows (bits) suppressing column c
        unsigned long long colT[64];
#pragma unroll
        for (int c = 0; c < 64; c++) {
            unsigned blo = __ballot_sync(FULL, (unsigned)((d0 >> c) & 1ull));
            unsigned bhi = __ballot_sync(FULL, (unsigned)((d1 >> c) & 1ull));
            colT[c] = ((unsigned long long)bhi << 32) | blo;
        }

        // serial resolve — registers only (strictly upper-triangular, so colT[bb]
        // references only rows < bb, all decided by the time bb is tested)
        unsigned long long aliveM = 0ull, supM = 0ull;
#pragma unroll
        for (int bb = 0; bb < 64; bb++) {
            unsigned long long hit = colT[bb] & aliveM;
            bool sup = (hit != 0ull);
            if (sup) supM |= (1ull << bb);
            else if ((elig >> bb) & 1ull) aliveM |= (1ull << bb);
        }

        if (lane == chunk) rem |= supM;      // intra-chunk suppression
        if (lane > chunk) {                  // later-chunk words of alive rows
#pragma unroll 8
            for (int bb = 0; bb < 64; bb++) {
                if ((aliveM >> bb) & 1ull)   // uniform branch (aliveM replicated)
                    rem |= g_mask[img][base + bb][lane];
            }
        }
    }
    g_removed[img][lane] = rem;
}

// ---------------- K6: write [B,N,6] output ----------------
__global__ void k6_out(float* __restrict__ out) {
    int t = blockIdx.x * blockDim.x + threadIdx.x;
    if (t >= BB * NN) return;
    int b = t / NN, p = t % NN;
    unsigned long long w = g_removed[b][p >> 6];
    bool rem = (w >> (p & 63)) & 1ull;
    bool keep = g_svalid[b][p] && !rem;
    float* o = out + ((size_t)b * NN + p) * 6;
    if (keep) {
        float4 bx = g_obox[b][p];
        o[0] = bx.x; o[1] = bx.y; o[2] = bx.z; o[3] = bx.w;
        o[4] = g_sscore[b][p];
        o[5] = (float)g_scls[b][p];
    } else {
        o[0] = 0.f; o[1] = 0.f; o[2] = 0.f; o[3] = 0.f; o[4] = 0.f; o[5] = 0.f;
    }
}

extern "C" void kernel_launch(void* const* d_in, const int* in_sizes, int n_in,
                              void* d_out, int out_size) {
    const float* prop  = (const float*)d_in[0];
    const float* preds = (const float*)d_in[1];
    const float* bsc   = (const float*)d_in[2];
    float* out = (float*)d_out;

    (void)in_sizes; (void)n_in; (void)out_size;

    k2_sort<<<BB, 1024>>>(prop, preds, bsc);
    int tot2 = BB * NN;
    k3_gather<<<(tot2 + 255) / 256, 256>>>(prop, preds, bsc);
    dim3 mg(NB64, NB64, BB);
    k4_mask<<<mg, 64>>>();
    k5_reduce<<<BB, 32>>>();
    k6_out<<<(tot2 + 255) / 256, 256>>>(out);
}